// round 3
// baseline (speedup 1.0000x reference)
#include <cuda_runtime.h>
#include <math.h>

#define B_ROWS 8192
#define C_COLS 32000
#define NBLOCK B_ROWS

// Scratch (no device allocation allowed in kernel_launch)
__device__ float g_row_loss[B_ROWS];
__device__ unsigned int g_done_count = 0;   // self-resetting ticket for last-block reduce

__device__ __forceinline__ void combine(float& m, float& s, float mo, float so) {
    float mn = fmaxf(m, mo);
    s = s * __expf(m - mn) + so * __expf(mo - mn);
    m = mn;
}

__global__ __launch_bounds__(256, 8)
void ce_fused_kernel(const float* __restrict__ x,
                     const int* __restrict__ y0w,        // raw 32-bit view of y0
                     const float* __restrict__ a1_freq,
                     const int* __restrict__ gramma_ptr, // may be null
                     float* __restrict__ out) {
    const int row = blockIdx.x;
    const int tid = threadIdx.x;
    const float4* __restrict__ xr =
        reinterpret_cast<const float4*>(x + (size_t)row * C_COLS);

    // ---- single-pass online softmax over this row (reads 128KB once) ----
    float m = -INFINITY;
    float s = 0.0f;

    const int nvec = C_COLS / 4;  // 8000 float4 per row
    for (int i = tid; i < nvec; i += 256) {
        float4 v = __ldg(&xr[i]);
        float vmax = fmaxf(fmaxf(v.x, v.y), fmaxf(v.z, v.w));
        if (vmax > m) {
            s *= __expf(m - vmax);
            m = vmax;
        }
        s += __expf(v.x - m);
        s += __expf(v.y - m);
        s += __expf(v.z - m);
        s += __expf(v.w - m);
    }

    // ---- warp reduce (m,s) ----
    #pragma unroll
    for (int o = 16; o > 0; o >>= 1) {
        float mo = __shfl_xor_sync(0xFFFFFFFFu, m, o);
        float so = __shfl_xor_sync(0xFFFFFFFFu, s, o);
        combine(m, s, mo, so);
    }

    // ---- block reduce across 8 warps ----
    __shared__ float sm_m[8];
    __shared__ float sm_s[8];
    __shared__ bool  sm_last;
    const int warp = tid >> 5;
    const int lane = tid & 31;
    if (lane == 0) { sm_m[warp] = m; sm_s[warp] = s; }
    __syncthreads();

    if (warp == 0) {
        m = (lane < 8) ? sm_m[lane] : -INFINITY;
        s = (lane < 8) ? sm_s[lane] : 0.0f;
        #pragma unroll
        for (int o = 4; o > 0; o >>= 1) {
            float mo = __shfl_xor_sync(0xFFFFFFFFu, m, o);
            float so = __shfl_xor_sync(0xFFFFFFFFu, s, o);
            combine(m, s, mo, so);
        }

        // ---- inline y0 dtype detection (warp-cooperative, L2 hits) ----
        // int64 LE => odd 32-bit words (high words) are all 0; int32 => class
        // indices, P(32 random words in [0,32000) all zero) ~ 0. Reads stay
        // within the first 256B of y0, valid for both layouts.
        int oddw = __ldg(&y0w[2 * lane + 1]);
        unsigned all0 = __ballot_sync(0xFFFFFFFFu, oddw == 0);
        bool is64 = (all0 == 0xFFFFFFFFu);

        if (lane == 0) {
            int t = is64 ? __ldg(&y0w[2 * row]) : __ldg(&y0w[row]);
            float xt = __ldg(&x[(size_t)row * C_COLS + (size_t)t]);
            int g = gramma_ptr ? __ldg(gramma_ptr) : 1;
            float tw = 2.0f * __ldg(&a1_freq[row]);
            float w = (g == 1) ? tw : powf(tw, (float)g);
            g_row_loss[row] = w * (xt - m - __logf(s));

            // release our row-loss, take a ticket
            __threadfence();
            unsigned ticket = atomicAdd(&g_done_count, 1u);
            sm_last = (ticket == (unsigned)(NBLOCK - 1));
        }
    }
    __syncthreads();

    // ---- last block: deterministic fixed-order final reduction ----
    if (sm_last) {
        __threadfence();  // acquire all g_row_loss writes
        float acc = 0.0f;
        #pragma unroll
        for (int i = tid; i < B_ROWS; i += 256) acc += g_row_loss[i];

        #pragma unroll
        for (int o = 16; o > 0; o >>= 1)
            acc += __shfl_xor_sync(0xFFFFFFFFu, acc, o);

        __shared__ float sm_r[8];
        if (lane == 0) sm_r[warp] = acc;
        __syncthreads();
        if (warp == 0) {
            acc = (lane < 8) ? sm_r[lane] : 0.0f;
            #pragma unroll
            for (int o = 4; o > 0; o >>= 1)
                acc += __shfl_xor_sync(0xFFFFFFFFu, acc, o);
            if (lane == 0) {
                out[0] = -acc / (float)B_ROWS;
                g_done_count = 0;   // reset for next graph replay
            }
        }
    }
}

extern "C" void kernel_launch(void* const* d_in, const int* in_sizes, int n_in,
                              void* d_out, int out_size) {
    const float* x   = (const float*)d_in[0];
    const int*   y0w = (const int*)d_in[1];
    const float* af  = (const float*)d_in[2];
    const int*   gr  = (n_in > 3) ? (const int*)d_in[3] : (const int*)0;
    float* out = (float*)d_out;

    ce_fused_kernel<<<NBLOCK, 256>>>(x, y0w, af, gr, out);
}